// round 15
// baseline (speedup 1.0000x reference)
#include <cuda_runtime.h>
#include <cstdint>

#define NVEC    131072
#define DDIM    128
#define KCODES  1024
#define BN      128          // vectors per CTA
#define BKC     64           // codes per chunk
#define NCHUNK  (KCODES / BKC)
#define NT      128

// smem floats: zs[128*128] + cs[128*64] + ss[1024] + rs[128] -> 103040 B
#define F_ZS 0
#define F_CS (DDIM * BN)
#define F_SS (F_CS + DDIM * BKC)
#define F_RS (F_SS + KCODES)
#define SMEM_BYTES ((F_RS + BN) * 4)

typedef unsigned long long u64;

__device__ float g_cbT[DDIM * KCODES];   // transposed codebook [d][k]
__device__ float g_snorm[KCODES];

// Fused prep: codebook transpose (all 128 blocks) + exact sequential
// ||c_k||^2 (blocks 0-3, bit-identical to the reference's square->sum).
// The snorm dependency chains overlap the transpose's gather latency.
__global__ void prep_kernel(const float* __restrict__ cb) {
    int tid = threadIdx.x;
    int idx = blockIdx.x * 256 + tid;      // 32768 threads
    int d = idx >> 8, kg = idx & 255;
    float4 v;
    v.x = cb[(4 * kg + 0) * DDIM + d];
    v.y = cb[(4 * kg + 1) * DDIM + d];
    v.z = cb[(4 * kg + 2) * DDIM + d];
    v.w = cb[(4 * kg + 3) * DDIM + d];
    *(float4*)(g_cbT + d * KCODES + 4 * kg) = v;

    if (blockIdx.x < 4) {
        int k = blockIdx.x * 256 + tid;    // 1024 snorm rows
        const float4* row = (const float4*)(cb + k * DDIM);
        float s = 0.f;
#pragma unroll
        for (int i = 0; i < 32; i++) {
            float4 w = row[i];
            s = __fadd_rn(s, __fmul_rn(w.x, w.x));
            s = __fadd_rn(s, __fmul_rn(w.y, w.y));
            s = __fadd_rn(s, __fmul_rn(w.z, w.z));
            s = __fadd_rn(s, __fmul_rn(w.w, w.w));
        }
        g_snorm[k] = s;
    }
}

// argmin + fused gather. 8 vectors x 8 codes per thread via FFMA2 (measured
// rt3 = the fastest MAC engine available at this compile target; mainloop is
// at the pipe floor). dist = fl( fl(r + s_k) - 2*p_k ), lowest-index
// tie-break; per-lane k order ascending (bit-identical tie semantics).
__global__ void __launch_bounds__(NT, 2)
argmin_kernel(const float* __restrict__ z, const float* __restrict__ cb,
              float* __restrict__ out) {
    extern __shared__ float smem[];
    float* zs = smem + F_ZS;     // [128][128] z tile, d-major
    float* cs = smem + F_CS;     // [128][64]  code tile, k-major
    float* ss = smem + F_SS;     // [1024]     snorm
    float* rs = smem + F_RS;     // [128]      ||z||^2 / later ids
    int*   ids = (int*)rs;

    const int tid = threadIdx.x;
    const int wid = tid >> 5, lane = tid & 31;
    const int vg = wid * 4 + (lane >> 3);  // vector group 0..15: vectors 8vg..8vg+7
    const int cg = lane & 7;               // code lane: codes cg + 8j, j<8

    const int nbase = blockIdx.x * BN;
    const int b  = nbase >> 12;
    const int hw = nbase & 4095;
    const float* zb = z + (size_t)b * (DDIM * 4096) + hw;

    // Fill zs: float4 gmem loads (coalesced over hw), float4 smem stores.
#pragma unroll
    for (int i = 0; i < 32; i++) {
        int idx = tid + i * NT;            // 4096 float4s
        int d = idx >> 5, v4 = idx & 31;
        *(float4*)(zs + d * BN + v4 * 4) =
            *(const float4*)(zb + (size_t)d * 4096 + v4 * 4);
    }
    // Stage snorm into smem (once).
#pragma unroll
    for (int i = 0; i < 2; i++) {
        int idx = tid + i * NT;            // 256 float4s
        *(float4*)(ss + idx * 4) = *(const float4*)(g_snorm + idx * 4);
    }
    __syncthreads();

    // r_n = sequential fp32 sum of squares over d = 0..127 in order.
    {
        float r = 0.f;
#pragma unroll
        for (int d = 0; d < DDIM; d++) {
            float v = zs[d * BN + tid];
            r = __fadd_rn(r, __fmul_rn(v, v));
        }
        rs[tid] = r;
    }
    __syncthreads();

    float rreg[8];
#pragma unroll
    for (int n = 0; n < 8; n++) rreg[n] = rs[8 * vg + n];

    float best[8];
    int   bidx[8];
#pragma unroll
    for (int n = 0; n < 8; n++) { best[n] = 3.4e38f; bidx[n] = 0; }

    for (int ch = 0; ch < NCHUNK; ch++) {
        __syncthreads();
        // Fill cs: contiguous 64-float rows of g_cbT (LDG.128 + STS.128).
        const float* gsrc = g_cbT + ch * BKC;
#pragma unroll
        for (int i = 0; i < 16; i++) {
            int idx = tid + i * NT;        // 2048 float4s
            int d = idx >> 4, k4 = idx & 15;
            *(float4*)(cs + d * BKC + k4 * 4) =
                *(const float4*)(gsrc + d * KCODES + k4 * 4);
        }
        __syncthreads();

        // acc[n2*8+j]: lo = vector 8vg+2n2, hi = 8vg+2n2+1, code cg+8j.
        u64 acc[32];
#pragma unroll
        for (int a = 0; a < 32; a++) acc[a] = 0ull;

#pragma unroll 4
        for (int d = 0; d < DDIM; d++) {
            const float* zrow = zs + d * BN + 8 * vg;  // 4 addrs/warp: broadcast
            u64 zp[4];
#pragma unroll
            for (int n2 = 0; n2 < 4; n2++)
                zp[n2] = *(const u64*)(zrow + 2 * n2);  // (z[2n2], z[2n2+1])
            const float* crow = cs + d * BKC + cg;      // 8 banks, 4-way bcast
#pragma unroll
            for (int j = 0; j < 8; j++) {
                float c = crow[8 * j];
                u64 cd;
                asm("mov.b64 %0, {%1, %1};" : "=l"(cd) : "f"(c));
#pragma unroll
                for (int n2 = 0; n2 < 4; n2++)
                    asm("fma.rn.f32x2 %0, %1, %2, %0;"
                        : "+l"(acc[n2 * 8 + j]) : "l"(zp[n2]), "l"(cd));
            }
        }

        // dist = fl( fl(r + s_k) - 2*p ); k ascending per lane (j asc, ch asc).
#pragma unroll
        for (int j = 0; j < 8; j++) {
            const int k = ch * BKC + cg + 8 * j;
            const float s = ss[k];
#pragma unroll
            for (int n2 = 0; n2 < 4; n2++) {
                u64 ap = acc[n2 * 8 + j];
                float plo = __uint_as_float((unsigned)(ap & 0xffffffffu));
                float phi = __uint_as_float((unsigned)(ap >> 32));
                int nlo = 2 * n2, nhi = 2 * n2 + 1;
                float dlo = __fmaf_rn(-2.f, plo, __fadd_rn(rreg[nlo], s));
                float dhi = __fmaf_rn(-2.f, phi, __fadd_rn(rreg[nhi], s));
                if (dlo < best[nlo] || (dlo == best[nlo] && k < bidx[nlo])) {
                    best[nlo] = dlo; bidx[nlo] = k;
                }
                if (dhi < best[nhi] || (dhi == best[nhi] && k < bidx[nhi])) {
                    best[nhi] = dhi; bidx[nhi] = k;
                }
            }
        }
    }

    // Reduce across the 8 lanes (cg = 0..7) sharing each vector group.
#pragma unroll
    for (int n = 0; n < 8; n++) {
        float v = best[n]; int id = bidx[n];
#pragma unroll
        for (int off = 4; off > 0; off >>= 1) {
            float v2 = __shfl_down_sync(0xffffffffu, v, off);
            int   i2 = __shfl_down_sync(0xffffffffu, id, off);
            if (v2 < v || (v2 == v && i2 < id)) { v = v2; id = i2; }
        }
        if (cg == 0) ids[8 * vg + n] = id;
    }
    __syncthreads();

    // Fused gather: out[b, i, hw+v] = cb[ids[v], i]; coalesced stores,
    // codebook reads L2-resident; hides under the co-resident CTA's FMA.
    float* ob = out + (size_t)b * (DDIM * 4096) + hw;
#pragma unroll
    for (int i = 0; i < DDIM; i++)
        ob[(size_t)i * 4096 + tid] = cb[ids[tid] * DDIM + i];
}

extern "C" void kernel_launch(void* const* d_in, const int* in_sizes, int n_in,
                              void* d_out, int out_size) {
    const float* z  = (const float*)d_in[0];
    const float* cb = (const float*)d_in[1];
    float* out = (float*)d_out;

    cudaFuncSetAttribute(argmin_kernel,
                         cudaFuncAttributeMaxDynamicSharedMemorySize, SMEM_BYTES);

    prep_kernel<<<128, 256>>>(cb);
    argmin_kernel<<<NVEC / BN, NT, SMEM_BYTES>>>(z, cb, out);
}